// round 15
// baseline (speedup 1.0000x reference)
#include <cuda_runtime.h>
#include <cuda_fp16.h>
#include <math.h>
#include <stdint.h>

#define NB   16384
#define HID  256
#define TOUT 16
#define MSPLIT 18

// ---------------- persistent device scratch ----------------
__device__ float  d_W4h[4][1024 * 256];   // permuted recurrent weights [col'][k] (fp32)
__device__ float  d_W4i[4][1024 * 4];
__device__ float  d_b4 [4][1024];
__device__ __half d_hbuf[4][2][NB * HID]; // hidden state, fp16
__device__ float  d_cbuf[4][NB * HID];    // cell state, fp32
__device__ __half d_h0c[NB * HID];
__device__ float  d_c0c[NB * HID];
__device__ float  d_xs[NB * 4];
__device__ float  d_xc[NB * 4];

__device__ __forceinline__ float sigf(float x) { return 1.0f / (1.0f + expf(-x)); }
__device__ __forceinline__ float sig_fast(float x) {
    float e = __expf(-x);
    return __fdividef(1.0f, 1.0f + e);
}
__device__ __forceinline__ float tanh_fast(float x) {
    float e = __expf(-2.0f * x);
    return (1.0f - e) * __fdividef(1.0f, 1.0f + e);
}
__device__ __forceinline__ float gclamp(float x) { return fminf(fmaxf(x, -30.0f), 30.0f); }

__device__ __forceinline__ void mma_f16acc(uint32_t* d,
    uint32_t a0, uint32_t a1, uint32_t a2, uint32_t a3, uint32_t b0, uint32_t b1) {
    asm volatile("mma.sync.aligned.m16n8k16.row.col.f16.f16.f16.f16 "
        "{%0,%1}, {%2,%3,%4,%5}, {%6,%7}, {%0,%1};"
        : "+r"(d[0]), "+r"(d[1])
        : "r"(a0), "r"(a1), "r"(a2), "r"(a3), "r"(b0), "r"(b1));
}

__device__ __forceinline__ __half2 H2(uint32_t u) { return *(__half2*)&u; }

// ---------------- SMEM layout ----------------
// 64-half chunks: 32 data words + 4 pad per row per chunk
#define AW 36
#define SM_WI   0                         // 128*4 floats = 2048 B
#define SM_BI   2048                      // 512 B
#define SM_A    2560                      // 2*128*36*4  = 36864 B
#define SM_B    39424                     // 4*128*36*4  = 73728 B
#define SM_TOTAL 113152                   // x2 = 226304 B  <  228KB/SM -> 2 CTAs co-resident

// ---------------- weight permutation ----------------
__global__ void prep_kernel(int cell,
                            const float* __restrict__ Whh,
                            const float* __restrict__ Wih,
                            const float* __restrict__ bih,
                            const float* __restrict__ bhh) {
    int colp = blockIdx.x;
    int k    = threadIdx.x;
    int g    = (colp & 127) >> 5;
    int u    = ((colp >> 7) << 5) + (colp & 31);
    int orig = g * 256 + u;
    d_W4h[cell][colp * 256 + k] = Whh[orig * 256 + k];
    if (k < 4) d_W4i[cell][colp * 4 + k] = Wih[orig * 4 + k];
    if (k == 0) d_b4[cell][colp] = bih[orig] + bhh[orig];
}

// ---------------- first step (h=c=0) ----------------
__global__ __launch_bounds__(256, 2) void cell_first_kernel(
    const float* __restrict__ x0, const float* __restrict__ x1, int xstride)
{
    int cell = blockIdx.z;
    const float* x = blockIdx.z == 0 ? x0 : x1;
    __half* hout = d_hbuf[cell][1];
    float*  cout = d_cbuf[cell];
    int row0 = blockIdx.y << 7;
    int col0 = blockIdx.x << 7;
    int tx = threadIdx.x & 15;
    int ty = threadIdx.x >> 4;

    float xv[8][4];
    #pragma unroll
    for (int rr = 0; rr < 8; rr++) {
        int row = row0 + (ty << 3) + rr;
        #pragma unroll
        for (int s = 0; s < 4; s++) xv[rr][s] = x[(size_t)row * xstride + s];
    }
    const float* Wi = d_W4i[cell];
    const float* bb = d_b4[cell];
    int ubase = blockIdx.x << 5;

    #pragma unroll
    for (int hh = 0; hh < 2; hh++) {
        int u = ubase + tx + (hh << 4);
        float wi[4][4], bg[4];
        #pragma unroll
        for (int g = 0; g < 4; g++) {
            int colp = col0 + (g << 5) + tx + (hh << 4);
            bg[g] = bb[colp];
            #pragma unroll
            for (int s = 0; s < 4; s++) wi[g][s] = Wi[colp * 4 + s];
        }
        #pragma unroll
        for (int rr = 0; rr < 8; rr++) {
            int row = row0 + (ty << 3) + rr;
            float gt[4];
            #pragma unroll
            for (int g = 0; g < 4; g++) {
                float v = bg[g];
                #pragma unroll
                for (int s = 0; s < 4; s++) v = fmaf(wi[g][s], xv[rr][s], v);
                gt[g] = v;
            }
            float ig = sigf(gt[0]);
            float gg = tanhf(gt[2]);
            float og = sigf(gt[3]);
            float cn = ig * gg;
            float hn = og * tanhf(cn);
            cout[(size_t)row * HID + u] = cn;
            hout[(size_t)row * HID + u] = __float2half(hn);
        }
    }
}

// ---------------- fp16 mma.sync LSTM step (64-half chunks, 2 CTAs/SM) ----------------
// grid (8 N-tiles, 2 cells, MSPLIT M-groups), 256 threads = 8 warps.
__global__ __launch_bounds__(256, 2) void cell_mma_kernel(
    int cell_base, const float* __restrict__ x0, const float* __restrict__ x1,
    int xstride, int rd, int use_comb, int use_fb)
{
    extern __shared__ char smem[];
    uint32_t* smA = (uint32_t*)(smem + SM_A);   // [2][128][AW]
    uint32_t* smB = (uint32_t*)(smem + SM_B);   // [4][128][AW]
    float* smWI = (float*)(smem + SM_WI);
    float* smBI = (float*)(smem + SM_BI);

    int tid = threadIdx.x;
    int wid = tid >> 5, lane = tid & 31;
    int gid = lane >> 2, tig = lane & 3;
    int cell = cell_base + blockIdx.y;
    const float* x = use_fb ? (blockIdx.y == 0 ? d_xs : d_xc)
                            : (blockIdx.y == 0 ? x0 : x1);
    const __half* hin = use_comb ? d_h0c : d_hbuf[cell][rd];
    const float*  cin = use_comb ? d_c0c : d_cbuf[cell];
    __half* hout = d_hbuf[cell][rd ^ 1];
    float*  cout = d_cbuf[cell];
    const float* Wh = d_W4h[cell];
    int nt = blockIdx.x;
    int col0 = nt << 7;
    int m_lo = (blockIdx.z * 128) / MSPLIT;
    int m_hi = ((blockIdx.z + 1) * 128) / MSPLIT;

    int r = tid >> 1, half = tid & 1;

    // ---- load resident weight tile (fp32 -> half2), Wi, bias ----
    {
        const float* wrow = Wh + (size_t)(col0 + r) * 256;
        #pragma unroll
        for (int c = 0; c < 4; c++) {
            const float* src = wrow + c * 64 + half * 32;
            uint32_t w[16];
            #pragma unroll
            for (int j = 0; j < 16; j++) {
                __half2 h2 = __floats2half2_rn(src[2 * j], src[2 * j + 1]);
                w[j] = *(uint32_t*)&h2;
            }
            uint32_t* dst = smB + ((size_t)c * 128 + r) * AW + half * 16;
            *(uint4*)(dst)      = make_uint4(w[0],  w[1],  w[2],  w[3]);
            *(uint4*)(dst + 4)  = make_uint4(w[4],  w[5],  w[6],  w[7]);
            *(uint4*)(dst + 8)  = make_uint4(w[8],  w[9],  w[10], w[11]);
            *(uint4*)(dst + 12) = make_uint4(w[12], w[13], w[14], w[15]);
        }
        if (tid < 128)
            *(float4*)(smWI + tid * 4) = *(const float4*)(d_W4i[cell] + (size_t)(col0 + tid) * 4);
        if (tid < 32)
            *(float4*)(smBI + tid * 4) = *(const float4*)(d_b4[cell] + col0 + tid * 4);
    }
    __syncthreads();

    // prologue: preload chunk 0 of first mtile (4 uint4 = 32 halves per thread)
    uint4 va[4];
    {
        const uint4* arow = (const uint4*)(hin + (size_t)((m_lo << 7) + r) * 256);
        #pragma unroll
        for (int j = 0; j < 4; j++) va[j] = arow[half * 4 + j];
    }

    for (int mt = m_lo; mt < m_hi; mt++) {
        int row0 = mt << 7;
        const uint4* arow = (const uint4*)(hin + (size_t)(row0 + r) * 256);

        uint32_t acc[16][2];
        #pragma unroll
        for (int i = 0; i < 16; i++) { acc[i][0] = 0u; acc[i][1] = 0u; }

        #pragma unroll
        for (int c = 0; c < 4; c++) {
            // stage current chunk
            uint32_t* dst = smA + (size_t)((c & 1) * 128 + r) * AW + half * 16;
            *(uint4*)(dst)      = va[0];
            *(uint4*)(dst + 4)  = va[1];
            *(uint4*)(dst + 8)  = va[2];
            *(uint4*)(dst + 12) = va[3];
            // prefetch next chunk BEFORE the barrier
            if (c < 3) {
                #pragma unroll
                for (int j = 0; j < 4; j++) va[j] = arow[(c + 1) * 8 + half * 4 + j];
            } else if (mt + 1 < m_hi) {
                const uint4* arow2 = (const uint4*)(hin + (size_t)(row0 + 128 + r) * 256);
                #pragma unroll
                for (int j = 0; j < 4; j++) va[j] = arow2[half * 4 + j];
            }
            __syncthreads();
            const uint32_t* Ab = smA + (size_t)((c & 1) * 128 + wid * 16) * AW;
            const uint32_t* Bb = smB + (size_t)c * 128 * AW;
            #pragma unroll
            for (int s = 0; s < 4; s++) {
                int kk = s * 8;
                uint32_t a0 = Ab[(size_t)gid * AW + kk + tig];
                uint32_t a1 = Ab[(size_t)(gid + 8) * AW + kk + tig];
                uint32_t a2 = Ab[(size_t)gid * AW + kk + tig + 4];
                uint32_t a3 = Ab[(size_t)(gid + 8) * AW + kk + tig + 4];
                #pragma unroll
                for (int n8 = 0; n8 < 16; n8++) {
                    uint32_t b0 = Bb[(size_t)(n8 * 8 + gid) * AW + kk + tig];
                    uint32_t b1 = Bb[(size_t)(n8 * 8 + gid) * AW + kk + tig + 4];
                    mma_f16acc(acc[n8], a0, a1, a2, a3, b0, b1);
                }
            }
        }

        // ---- fused LSTM epilogue (fast activations) ----
        #pragma unroll
        for (int rr = 0; rr < 2; rr++) {
            int row = row0 + wid * 16 + gid + rr * 8;
            float xv[4];
            #pragma unroll
            for (int s = 0; s < 4; s++) xv[s] = x[(size_t)row * xstride + s];
            #pragma unroll
            for (int j = 0; j < 4; j++) {
                int ub = 8 * j + 2 * tig;
                float2 cold = *(const float2*)(cin + (size_t)row * HID + nt * 32 + ub);
                float2 vi = __half22float2(H2(acc[j     ][rr]));
                float2 vf = __half22float2(H2(acc[j +  4][rr]));
                float2 vg = __half22float2(H2(acc[j +  8][rr]));
                float2 vo = __half22float2(H2(acc[j + 12][rr]));
                float hv[2], cv[2];
                #pragma unroll
                for (int e = 0; e < 2; e++) {
                    int u = ub + e;
                    float g_i = (e == 0 ? vi.x : vi.y) + smBI[u];
                    float g_f = (e == 0 ? vf.x : vf.y) + smBI[32 + u];
                    float g_g = (e == 0 ? vg.x : vg.y) + smBI[64 + u];
                    float g_o = (e == 0 ? vo.x : vo.y) + smBI[96 + u];
                    #pragma unroll
                    for (int s = 0; s < 4; s++) {
                        g_i = fmaf(smWI[u * 4 + s],        xv[s], g_i);
                        g_f = fmaf(smWI[(32 + u) * 4 + s], xv[s], g_f);
                        g_g = fmaf(smWI[(64 + u) * 4 + s], xv[s], g_g);
                        g_o = fmaf(smWI[(96 + u) * 4 + s], xv[s], g_o);
                    }
                    float co = (e == 0) ? cold.x : cold.y;
                    float cn = fmaf(sig_fast(gclamp(g_f)), co,
                                    sig_fast(gclamp(g_i)) * tanh_fast(gclamp(g_g)));
                    float hn = sig_fast(gclamp(g_o)) * tanh_fast(gclamp(cn));
                    cv[e] = cn; hv[e] = hn;
                }
                *(float2*)(cout + (size_t)row * HID + nt * 32 + ub) = make_float2(cv[0], cv[1]);
                *(__half2*)(hout + (size_t)row * HID + nt * 32 + ub) = __floats2half2_rn(hv[0], hv[1]);
            }
        }
    }
}

// ---------------- combine encoder finals ----------------
__global__ void combine_kernel() {
    size_t i = (size_t)blockIdx.x * blockDim.x + threadIdx.x;
    float4 c0 = ((const float4*)d_cbuf[0])[i];
    float4 c1 = ((const float4*)d_cbuf[1])[i];
    ((float4*)d_c0c)[i] = make_float4(c0.x + c1.x, c0.y + c1.y, c0.z + c1.z, c0.w + c1.w);
    const __half2* ha = (const __half2*)d_hbuf[0][0];
    const __half2* hb = (const __half2*)d_hbuf[1][0];
    __half2* ho = (__half2*)d_h0c;
    #pragma unroll
    for (int j = 0; j < 2; j++) {
        float2 a = __half22float2(ha[2 * i + j]);
        float2 b = __half22float2(hb[2 * i + j]);
        ho[2 * i + j] = __floats2half2_rn(a.x + b.x, a.y + b.y);
    }
}

// ---------------- decoder heads ----------------
__global__ void heads_kernel(int t, int parity,
    const float* __restrict__ fsw, const float* __restrict__ fsb,
    const float* __restrict__ fcw, const float* __restrict__ fcb,
    const float* __restrict__ ew,  const float* __restrict__ eb,
    float* __restrict__ out)
{
    int gtid = blockIdx.x * blockDim.x + threadIdx.x;
    int row  = gtid >> 5;
    int lane = gtid & 31;
    if (row >= NB) return;
    const __half* hs = d_hbuf[2][parity] + (size_t)row * HID;
    const __half* hc = d_hbuf[3][parity] + (size_t)row * HID;
    float vs[8], vc[8];
    #pragma unroll
    for (int i = 0; i < 8; i++) {
        vs[i] = __half2float(hs[lane + 32 * i]);
        vc[i] = __half2float(hc[lane + 32 * i]);
    }

    float r[10];
    #pragma unroll
    for (int o = 0; o < 4; o++) {
        float p = 0.f;
        #pragma unroll
        for (int i = 0; i < 8; i++) p = fmaf(fsw[o * 256 + lane + 32 * i], vs[i], p);
        r[o] = p;
    }
    #pragma unroll
    for (int o = 0; o < 2; o++) {
        float p = 0.f;
        #pragma unroll
        for (int i = 0; i < 8; i++) p = fmaf(fcw[o * 256 + lane + 32 * i], vc[i], p);
        r[4 + o] = p;
    }
    #pragma unroll
    for (int o = 0; o < 4; o++) {
        float p = 0.f;
        #pragma unroll
        for (int i = 0; i < 8; i++) p = fmaf(ew[o * 256 + lane + 32 * i], vc[i], p);
        r[6 + o] = p;
    }
    #pragma unroll
    for (int off = 16; off > 0; off >>= 1)
        #pragma unroll
        for (int o = 0; o < 10; o++) r[o] += __shfl_xor_sync(0xffffffffu, r[o], off);

    if (lane == 0) {
        #pragma unroll
        for (int s = 0; s < 4; s++) {
            float v = r[s] + fsb[s];
            v = fminf(fmaxf(v, -100.f), 100.f);
            out[(size_t)row * 64 + t * 4 + s] = v;
            d_xs[row * 4 + s] = v;
        }
        float l0 = fmaxf(r[4] + fcb[0], 0.f);
        float l1 = fmaxf(r[5] + fcb[1], 0.f);
        float m  = fmaxf(l0, l1);
        float e0 = expf(l0 - m), e1 = expf(l1 - m);
        float inv = 1.f / (e0 + e1);
        size_t cb = (size_t)NB * 64;
        out[cb + (size_t)row * 32 + t * 2 + 0] = e0 * inv;
        out[cb + (size_t)row * 32 + t * 2 + 1] = e1 * inv;
        #pragma unroll
        for (int s = 0; s < 4; s++) d_xc[row * 4 + s] = fmaxf(r[6 + s] + eb[s], 0.f);
    }
}

// ---------------- host ----------------
extern "C" void kernel_launch(void* const* d_in, const int* in_sizes, int n_in,
                              void* d_out, int out_size)
{
    (void)in_sizes; (void)n_in; (void)out_size;
    const float* speed = (const float*)d_in[0];
    const float* pos   = (const float*)d_in[1];

    cudaFuncSetAttribute(cell_mma_kernel, cudaFuncAttributeMaxDynamicSharedMemorySize, SM_TOTAL);

    for (int cell = 0; cell < 4; cell++) {
        int base = 2 + 4 * cell;
        prep_kernel<<<1024, 256>>>(cell,
            (const float*)d_in[base + 1],
            (const float*)d_in[base + 0],
            (const float*)d_in[base + 2],
            (const float*)d_in[base + 3]);
    }

    dim3 tgrid(8, 2, MSPLIT);

    // ---- encoders ----
    cell_first_kernel<<<dim3(8, 128, 2), 256>>>(speed, pos, 64);
    for (int t = 1; t < 16; t++)
        cell_mma_kernel<<<tgrid, 256, SM_TOTAL>>>(0, speed + 4 * t, pos + 4 * t, 64, t & 1, 0, 0);

    combine_kernel<<<4096, 256>>>();

    // ---- decoders ----
    const float* fsw = (const float*)d_in[18];
    const float* fsb = (const float*)d_in[19];
    const float* fcw = (const float*)d_in[20];
    const float* fcb = (const float*)d_in[21];
    const float* ew  = (const float*)d_in[22];
    const float* eb  = (const float*)d_in[23];
    float* out = (float*)d_out;

    for (int t = 0; t < TOUT; t++) {
        if (t == 0)
            cell_mma_kernel<<<tgrid, 256, SM_TOTAL>>>(2, speed + 60, pos + 60, 64, 0, 1, 0);
        else
            cell_mma_kernel<<<tgrid, 256, SM_TOTAL>>>(2, nullptr, nullptr, 4, t & 1, 0, 1);
        heads_kernel<<<2048, 256>>>(t, (t & 1) ^ 1, fsw, fsb, fcw, fcb, ew, eb, out);
    }
}

// round 16
// speedup vs baseline: 1.3655x; 1.3655x over previous
#include <cuda_runtime.h>
#include <cuda_fp16.h>
#include <math.h>
#include <stdint.h>

#define NB   16384
#define HID  256
#define TOUT 16
#define MSPLIT 9

// ---------------- persistent device scratch ----------------
__device__ __half d_W4hh[4][1024 * 256];  // permuted recurrent weights, fp16 [col'][k]
__device__ float  d_W4i[4][1024 * 4];
__device__ float  d_b4 [4][1024];
__device__ __half d_hbuf[4][2][NB * HID]; // hidden state, fp16
__device__ float  d_cbuf[4][NB * HID];    // cell state, fp32
__device__ __half d_h0c[NB * HID];
__device__ float  d_c0c[NB * HID];
__device__ float  d_xs[NB * 4];
__device__ float  d_xc[NB * 4];

__device__ __forceinline__ float sigf(float x) { return 1.0f / (1.0f + expf(-x)); }
__device__ __forceinline__ float sig_fast(float x) {
    float e = __expf(-x);
    return __fdividef(1.0f, 1.0f + e);
}
__device__ __forceinline__ float tanh_fast(float x) {
    float e = __expf(-2.0f * x);
    return (1.0f - e) * __fdividef(1.0f, 1.0f + e);
}
__device__ __forceinline__ float gclamp(float x) { return fminf(fmaxf(x, -30.0f), 30.0f); }

__device__ __forceinline__ void mma_f16acc(uint32_t* d,
    uint32_t a0, uint32_t a1, uint32_t a2, uint32_t a3, uint32_t b0, uint32_t b1) {
    asm volatile("mma.sync.aligned.m16n8k16.row.col.f16.f16.f16.f16 "
        "{%0,%1}, {%2,%3,%4,%5}, {%6,%7}, {%0,%1};"
        : "+r"(d[0]), "+r"(d[1])
        : "r"(a0), "r"(a1), "r"(a2), "r"(a3), "r"(b0), "r"(b1));
}

__device__ __forceinline__ __half2 H2(uint32_t u) { return *(__half2*)&u; }

// ---------------- SMEM layout ----------------
// 64-half chunks: 32 data words + 4 pad per row per chunk
#define AW 36
#define SM_WI   0                         // 128*4 floats = 2048 B
#define SM_BI   2048                      // 512 B
#define SM_A    2560                      // 2*128*36*4  = 36864 B
#define SM_B    39424                     // 4*128*36*4  = 73728 B
#define SM_TOTAL 113152

// ---------------- weight permutation + fp16 pre-conversion ----------------
__global__ void prep_kernel(int cell,
                            const float* __restrict__ Whh,
                            const float* __restrict__ Wih,
                            const float* __restrict__ bih,
                            const float* __restrict__ bhh) {
    int colp = blockIdx.x;
    int k    = threadIdx.x;
    int g    = (colp & 127) >> 5;
    int u    = ((colp >> 7) << 5) + (colp & 31);
    int orig = g * 256 + u;
    d_W4hh[cell][colp * 256 + k] = __float2half(Whh[orig * 256 + k]);
    if (k < 4) d_W4i[cell][colp * 4 + k] = Wih[orig * 4 + k];
    if (k == 0) d_b4[cell][colp] = bih[orig] + bhh[orig];
}

// ---------------- first step (h=c=0) ----------------
__global__ __launch_bounds__(256, 2) void cell_first_kernel(
    const float* __restrict__ x0, const float* __restrict__ x1, int xstride)
{
    int cell = blockIdx.z;
    const float* x = blockIdx.z == 0 ? x0 : x1;
    __half* hout = d_hbuf[cell][1];
    float*  cout = d_cbuf[cell];
    int row0 = blockIdx.y << 7;
    int col0 = blockIdx.x << 7;
    int tx = threadIdx.x & 15;
    int ty = threadIdx.x >> 4;

    float xv[8][4];
    #pragma unroll
    for (int rr = 0; rr < 8; rr++) {
        int row = row0 + (ty << 3) + rr;
        #pragma unroll
        for (int s = 0; s < 4; s++) xv[rr][s] = x[(size_t)row * xstride + s];
    }
    const float* Wi = d_W4i[cell];
    const float* bb = d_b4[cell];
    int ubase = blockIdx.x << 5;

    #pragma unroll
    for (int hh = 0; hh < 2; hh++) {
        int u = ubase + tx + (hh << 4);
        float wi[4][4], bg[4];
        #pragma unroll
        for (int g = 0; g < 4; g++) {
            int colp = col0 + (g << 5) + tx + (hh << 4);
            bg[g] = bb[colp];
            #pragma unroll
            for (int s = 0; s < 4; s++) wi[g][s] = Wi[colp * 4 + s];
        }
        #pragma unroll
        for (int rr = 0; rr < 8; rr++) {
            int row = row0 + (ty << 3) + rr;
            float gt[4];
            #pragma unroll
            for (int g = 0; g < 4; g++) {
                float v = bg[g];
                #pragma unroll
                for (int s = 0; s < 4; s++) v = fmaf(wi[g][s], xv[rr][s], v);
                gt[g] = v;
            }
            float ig = sigf(gt[0]);
            float gg = tanhf(gt[2]);
            float og = sigf(gt[3]);
            float cn = ig * gg;
            float hn = og * tanhf(cn);
            cout[(size_t)row * HID + u] = cn;
            hout[(size_t)row * HID + u] = __float2half(hn);
        }
    }
}

// ---------------- fp16 mma.sync LSTM step (64-half chunks, 4 syncs/mtile) ----------------
// grid (8 N-tiles, 2 cells, MSPLIT M-groups), 256 threads = 8 warps.
__global__ __launch_bounds__(256, 1) void cell_mma_kernel(
    int cell_base, const float* __restrict__ x0, const float* __restrict__ x1,
    int xstride, int rd, int use_comb, int use_fb)
{
    extern __shared__ char smem[];
    uint32_t* smA = (uint32_t*)(smem + SM_A);   // [2][128][AW]
    uint32_t* smB = (uint32_t*)(smem + SM_B);   // [4][128][AW]
    float* smWI = (float*)(smem + SM_WI);
    float* smBI = (float*)(smem + SM_BI);

    int tid = threadIdx.x;
    int wid = tid >> 5, lane = tid & 31;
    int gid = lane >> 2, tig = lane & 3;
    int cell = cell_base + blockIdx.y;
    const float* x = use_fb ? (blockIdx.y == 0 ? d_xs : d_xc)
                            : (blockIdx.y == 0 ? x0 : x1);
    const __half* hin = use_comb ? d_h0c : d_hbuf[cell][rd];
    const float*  cin = use_comb ? d_c0c : d_cbuf[cell];
    __half* hout = d_hbuf[cell][rd ^ 1];
    float*  cout = d_cbuf[cell];
    const __half* Wh = d_W4hh[cell];
    int nt = blockIdx.x;
    int col0 = nt << 7;
    int m_lo = (blockIdx.z * 128) / MSPLIT;
    int m_hi = ((blockIdx.z + 1) * 128) / MSPLIT;

    int r = tid >> 1, half = tid & 1;

    // ---- load resident weight tile (pre-converted fp16, pure copy), Wi, bias ----
    {
        const __half* wrow = Wh + (size_t)(col0 + r) * 256;
        #pragma unroll
        for (int c = 0; c < 4; c++) {
            const uint4* src = (const uint4*)(wrow + c * 64 + half * 32);  // 32 halves = 4 uint4
            uint4 w0 = src[0], w1 = src[1], w2 = src[2], w3 = src[3];
            uint32_t* dst = smB + ((size_t)c * 128 + r) * AW + half * 16;
            *(uint4*)(dst)      = w0;
            *(uint4*)(dst + 4)  = w1;
            *(uint4*)(dst + 8)  = w2;
            *(uint4*)(dst + 12) = w3;
        }
        if (tid < 128)
            *(float4*)(smWI + tid * 4) = *(const float4*)(d_W4i[cell] + (size_t)(col0 + tid) * 4);
        if (tid < 32)
            *(float4*)(smBI + tid * 4) = *(const float4*)(d_b4[cell] + col0 + tid * 4);
    }
    __syncthreads();

    // prologue: preload chunk 0 of first mtile (4 uint4 = 32 halves per thread)
    uint4 va[4];
    {
        const uint4* arow = (const uint4*)(hin + (size_t)((m_lo << 7) + r) * 256);
        #pragma unroll
        for (int j = 0; j < 4; j++) va[j] = arow[half * 4 + j];
    }

    for (int mt = m_lo; mt < m_hi; mt++) {
        int row0 = mt << 7;
        const uint4* arow = (const uint4*)(hin + (size_t)(row0 + r) * 256);

        uint32_t acc[16][2];
        #pragma unroll
        for (int i = 0; i < 16; i++) { acc[i][0] = 0u; acc[i][1] = 0u; }

        #pragma unroll
        for (int c = 0; c < 4; c++) {
            // stage current chunk
            uint32_t* dst = smA + (size_t)((c & 1) * 128 + r) * AW + half * 16;
            *(uint4*)(dst)      = va[0];
            *(uint4*)(dst + 4)  = va[1];
            *(uint4*)(dst + 8)  = va[2];
            *(uint4*)(dst + 12) = va[3];
            // prefetch next chunk BEFORE the barrier
            if (c < 3) {
                #pragma unroll
                for (int j = 0; j < 4; j++) va[j] = arow[(c + 1) * 8 + half * 4 + j];
            } else if (mt + 1 < m_hi) {
                const uint4* arow2 = (const uint4*)(hin + (size_t)(row0 + 128 + r) * 256);
                #pragma unroll
                for (int j = 0; j < 4; j++) va[j] = arow2[half * 4 + j];
            }
            __syncthreads();
            const uint32_t* Ab = smA + (size_t)((c & 1) * 128 + wid * 16) * AW;
            const uint32_t* Bb = smB + (size_t)c * 128 * AW;
            #pragma unroll
            for (int s = 0; s < 4; s++) {
                int kk = s * 8;
                uint32_t a0 = Ab[(size_t)gid * AW + kk + tig];
                uint32_t a1 = Ab[(size_t)(gid + 8) * AW + kk + tig];
                uint32_t a2 = Ab[(size_t)gid * AW + kk + tig + 4];
                uint32_t a3 = Ab[(size_t)(gid + 8) * AW + kk + tig + 4];
                #pragma unroll
                for (int n8 = 0; n8 < 16; n8++) {
                    uint32_t b0 = Bb[(size_t)(n8 * 8 + gid) * AW + kk + tig];
                    uint32_t b1 = Bb[(size_t)(n8 * 8 + gid) * AW + kk + tig + 4];
                    mma_f16acc(acc[n8], a0, a1, a2, a3, b0, b1);
                }
            }
        }

        // ---- fused LSTM epilogue (fast activations) ----
        #pragma unroll
        for (int rr = 0; rr < 2; rr++) {
            int row = row0 + wid * 16 + gid + rr * 8;
            float xv[4];
            #pragma unroll
            for (int s = 0; s < 4; s++) xv[s] = x[(size_t)row * xstride + s];
            #pragma unroll
            for (int j = 0; j < 4; j++) {
                int ub = 8 * j + 2 * tig;
                float2 cold = *(const float2*)(cin + (size_t)row * HID + nt * 32 + ub);
                float2 vi = __half22float2(H2(acc[j     ][rr]));
                float2 vf = __half22float2(H2(acc[j +  4][rr]));
                float2 vg = __half22float2(H2(acc[j +  8][rr]));
                float2 vo = __half22float2(H2(acc[j + 12][rr]));
                float hv[2], cv[2];
                #pragma unroll
                for (int e = 0; e < 2; e++) {
                    int u = ub + e;
                    float g_i = (e == 0 ? vi.x : vi.y) + smBI[u];
                    float g_f = (e == 0 ? vf.x : vf.y) + smBI[32 + u];
                    float g_g = (e == 0 ? vg.x : vg.y) + smBI[64 + u];
                    float g_o = (e == 0 ? vo.x : vo.y) + smBI[96 + u];
                    #pragma unroll
                    for (int s = 0; s < 4; s++) {
                        g_i = fmaf(smWI[u * 4 + s],        xv[s], g_i);
                        g_f = fmaf(smWI[(32 + u) * 4 + s], xv[s], g_f);
                        g_g = fmaf(smWI[(64 + u) * 4 + s], xv[s], g_g);
                        g_o = fmaf(smWI[(96 + u) * 4 + s], xv[s], g_o);
                    }
                    float co = (e == 0) ? cold.x : cold.y;
                    float cn = fmaf(sig_fast(gclamp(g_f)), co,
                                    sig_fast(gclamp(g_i)) * tanh_fast(gclamp(g_g)));
                    float hn = sig_fast(gclamp(g_o)) * tanh_fast(gclamp(cn));
                    cv[e] = cn; hv[e] = hn;
                }
                *(float2*)(cout + (size_t)row * HID + nt * 32 + ub) = make_float2(cv[0], cv[1]);
                *(__half2*)(hout + (size_t)row * HID + nt * 32 + ub) = __floats2half2_rn(hv[0], hv[1]);
            }
        }
    }
}

// ---------------- combine encoder finals ----------------
__global__ void combine_kernel() {
    size_t i = (size_t)blockIdx.x * blockDim.x + threadIdx.x;
    float4 c0 = ((const float4*)d_cbuf[0])[i];
    float4 c1 = ((const float4*)d_cbuf[1])[i];
    ((float4*)d_c0c)[i] = make_float4(c0.x + c1.x, c0.y + c1.y, c0.z + c1.z, c0.w + c1.w);
    const __half2* ha = (const __half2*)d_hbuf[0][0];
    const __half2* hb = (const __half2*)d_hbuf[1][0];
    __half2* ho = (__half2*)d_h0c;
    #pragma unroll
    for (int j = 0; j < 2; j++) {
        float2 a = __half22float2(ha[2 * i + j]);
        float2 b = __half22float2(hb[2 * i + j]);
        ho[2 * i + j] = __floats2half2_rn(a.x + b.x, a.y + b.y);
    }
}

// ---------------- decoder heads ----------------
__global__ void heads_kernel(int t, int parity,
    const float* __restrict__ fsw, const float* __restrict__ fsb,
    const float* __restrict__ fcw, const float* __restrict__ fcb,
    const float* __restrict__ ew,  const float* __restrict__ eb,
    float* __restrict__ out)
{
    int gtid = blockIdx.x * blockDim.x + threadIdx.x;
    int row  = gtid >> 5;
    int lane = gtid & 31;
    if (row >= NB) return;
    const __half* hs = d_hbuf[2][parity] + (size_t)row * HID;
    const __half* hc = d_hbuf[3][parity] + (size_t)row * HID;
    float vs[8], vc[8];
    #pragma unroll
    for (int i = 0; i < 8; i++) {
        vs[i] = __half2float(hs[lane + 32 * i]);
        vc[i] = __half2float(hc[lane + 32 * i]);
    }

    float r[10];
    #pragma unroll
    for (int o = 0; o < 4; o++) {
        float p = 0.f;
        #pragma unroll
        for (int i = 0; i < 8; i++) p = fmaf(fsw[o * 256 + lane + 32 * i], vs[i], p);
        r[o] = p;
    }
    #pragma unroll
    for (int o = 0; o < 2; o++) {
        float p = 0.f;
        #pragma unroll
        for (int i = 0; i < 8; i++) p = fmaf(fcw[o * 256 + lane + 32 * i], vc[i], p);
        r[4 + o] = p;
    }
    #pragma unroll
    for (int o = 0; o < 4; o++) {
        float p = 0.f;
        #pragma unroll
        for (int i = 0; i < 8; i++) p = fmaf(ew[o * 256 + lane + 32 * i], vc[i], p);
        r[6 + o] = p;
    }
    #pragma unroll
    for (int off = 16; off > 0; off >>= 1)
        #pragma unroll
        for (int o = 0; o < 10; o++) r[o] += __shfl_xor_sync(0xffffffffu, r[o], off);

    if (lane == 0) {
        #pragma unroll
        for (int s = 0; s < 4; s++) {
            float v = r[s] + fsb[s];
            v = fminf(fmaxf(v, -100.f), 100.f);
            out[(size_t)row * 64 + t * 4 + s] = v;
            d_xs[row * 4 + s] = v;
        }
        float l0 = fmaxf(r[4] + fcb[0], 0.f);
        float l1 = fmaxf(r[5] + fcb[1], 0.f);
        float m  = fmaxf(l0, l1);
        float e0 = expf(l0 - m), e1 = expf(l1 - m);
        float inv = 1.f / (e0 + e1);
        size_t cb = (size_t)NB * 64;
        out[cb + (size_t)row * 32 + t * 2 + 0] = e0 * inv;
        out[cb + (size_t)row * 32 + t * 2 + 1] = e1 * inv;
        #pragma unroll
        for (int s = 0; s < 4; s++) d_xc[row * 4 + s] = fmaxf(r[6 + s] + eb[s], 0.f);
    }
}

// ---------------- host ----------------
extern "C" void kernel_launch(void* const* d_in, const int* in_sizes, int n_in,
                              void* d_out, int out_size)
{
    (void)in_sizes; (void)n_in; (void)out_size;
    const float* speed = (const float*)d_in[0];
    const float* pos   = (const float*)d_in[1];

    cudaFuncSetAttribute(cell_mma_kernel, cudaFuncAttributeMaxDynamicSharedMemorySize, SM_TOTAL);

    for (int cell = 0; cell < 4; cell++) {
        int base = 2 + 4 * cell;
        prep_kernel<<<1024, 256>>>(cell,
            (const float*)d_in[base + 1],
            (const float*)d_in[base + 0],
            (const float*)d_in[base + 2],
            (const float*)d_in[base + 3]);
    }

    dim3 tgrid(8, 2, MSPLIT);

    // ---- encoders ----
    cell_first_kernel<<<dim3(8, 128, 2), 256>>>(speed, pos, 64);
    for (int t = 1; t < 16; t++)
        cell_mma_kernel<<<tgrid, 256, SM_TOTAL>>>(0, speed + 4 * t, pos + 4 * t, 64, t & 1, 0, 0);

    combine_kernel<<<4096, 256>>>();

    // ---- decoders ----
    const float* fsw = (const float*)d_in[18];
    const float* fsb = (const float*)d_in[19];
    const float* fcw = (const float*)d_in[20];
    const float* fcb = (const float*)d_in[21];
    const float* ew  = (const float*)d_in[22];
    const float* eb  = (const float*)d_in[23];
    float* out = (float*)d_out;

    for (int t = 0; t < TOUT; t++) {
        if (t == 0)
            cell_mma_kernel<<<tgrid, 256, SM_TOTAL>>>(2, speed + 60, pos + 60, 64, 0, 1, 0);
        else
            cell_mma_kernel<<<tgrid, 256, SM_TOTAL>>>(2, nullptr, nullptr, 4, t & 1, 0, 1);
        heads_kernel<<<2048, 256>>>(t, (t & 1) ^ 1, fsw, fsb, fcw, fcb, ew, eb, out);
    }
}